// round 9
// baseline (speedup 1.0000x reference)
#include <cuda_runtime.h>
#include <cuda_fp16.h>
#include <cstdint>

// Problem constants
#define BB   8
#define CC   512
#define NPIX 4096
#define OC   1536
#define NQ   (OC / 4)      // quad-channel groups = 384
#define ND   4
#define BD   128
#define HD   64

// Scratch (static device allocations — allowed)
// Packed-quad fp16 qkv: layout [b][qidx][n][4], qidx = (c>>5)*8 + (c&7),
// sub = (c>>3)&3 → pixel n holds channels (c0, c0+8, c0+16, c0+24).
__device__ __align__(16) __half g_qh[(size_t)BB * OC * NPIX];   // 96 MB
__device__ float g_pooled[BB * CC];
__device__ float g_gate[BB * ND];
__device__ __align__(16) __half g_wh[OC * CC];                  // fp16 w
__device__ __align__(16) __half g_xh[(size_t)BB * NPIX * CC];   // fp16 x, [b][n][c]

// ---------------------------------------------------------------------------
// PTX helpers (sm_80+ only)
// ---------------------------------------------------------------------------
__device__ __forceinline__ uint32_t smem_u32(const void* p) {
    uint32_t a;
    asm("{ .reg .u64 t; cvta.to.shared.u64 t, %1; cvt.u32.u64 %0, t; }"
        : "=r"(a) : "l"(p));
    return a;
}
__device__ __forceinline__ void cp_async16(uint32_t s, const void* g) {
    asm volatile("cp.async.cg.shared.global [%0], [%1], 16;" :: "r"(s), "l"(g));
}
__device__ __forceinline__ void cp_commit() {
    asm volatile("cp.async.commit_group;" ::: "memory");
}
template <int N>
__device__ __forceinline__ void cp_wait() {
    asm volatile("cp.async.wait_group %0;" :: "n"(N) : "memory");
}
__device__ __forceinline__ void ldsm_x4(uint32_t& r0, uint32_t& r1,
                                        uint32_t& r2, uint32_t& r3, uint32_t a) {
    asm volatile("ldmatrix.sync.aligned.m8n8.x4.shared.b16 {%0,%1,%2,%3}, [%4];"
                 : "=r"(r0), "=r"(r1), "=r"(r2), "=r"(r3) : "r"(a));
}
__device__ __forceinline__ void mma_fp16(float* d, const uint32_t* a, const uint32_t* b) {
    asm volatile("mma.sync.aligned.m16n8k16.row.col.f32.f16.f16.f32 "
                 "{%0,%1,%2,%3}, {%4,%5,%6,%7}, {%8,%9}, {%0,%1,%2,%3};"
                 : "+f"(d[0]), "+f"(d[1]), "+f"(d[2]), "+f"(d[3])
                 : "r"(a[0]), "r"(a[1]), "r"(a[2]), "r"(a[3]),
                   "r"(b[0]), "r"(b[1]));
}
__device__ __forceinline__ uint32_t h2bits(__half2 h) {
    return *reinterpret_cast<uint32_t*>(&h);
}

// ---------------------------------------------------------------------------
// Pre-pass 1: w -> fp16, fused zeroing of the pooled accumulator
// ---------------------------------------------------------------------------
__global__ __launch_bounds__(256) void split_w_kernel(const float* __restrict__ w)
{
    int i = blockIdx.x * 256 + threadIdx.x;
    g_wh[i] = __float2half(w[i]);
    if (i < BB * CC) g_pooled[i] = 0.f;
}

// ---------------------------------------------------------------------------
// Pre-pass 2: transpose x [b][c][n] -> [b][n][c] as fp16, fused mean-pool
// partial sums (atomicAdd raw sums; gate divides by NPIX).
// ---------------------------------------------------------------------------
__global__ __launch_bounds__(256) void tsx_kernel(const float* __restrict__ x)
{
    __shared__ float t[32][33];
    const int b  = blockIdx.z;
    const int n0 = blockIdx.x * 32;
    const int c0 = blockIdx.y * 32;
    const int tx = threadIdx.x, ty = threadIdx.y;

    #pragma unroll
    for (int i = ty; i < 32; i += 8)
        t[i][tx] = x[((size_t)b * CC + c0 + i) * NPIX + n0 + tx];
    __syncthreads();

    float psum = 0.f;
    #pragma unroll
    for (int i = ty; i < 32; i += 8) {
        float v = t[tx][i];   // x[c0+tx][n0+i]
        psum += v;
        g_xh[((size_t)b * NPIX + n0 + i) * CC + c0 + tx] = __float2half(v);
    }
    __syncthreads();
    t[ty][tx] = psum;
    __syncthreads();
    if (ty == 0) {
        float s = 0.f;
        #pragma unroll
        for (int j = 0; j < 8; j++) s += t[j][tx];
        atomicAdd(&g_pooled[b * CC + c0 + tx], s);
    }
}

// ---------------------------------------------------------------------------
// fp16 GEMM via mma.sync: qkv[b][o][n] = sum_c w[o][c] x[b][c][n]
// 128x128 CTA tile, 4 warps (2m x 2n), warp tile 64x64, K chunk 32,
// 3-stage cp.async pipeline. Epilogue: fp16 packed-quad stores.
// ---------------------------------------------------------------------------
#define KC        32
#define ROWB      80               // 32 fp16 = 64B + 16B pad
#define TILE_SZ   (128 * ROWB)     // 10240B
#define T_A       0
#define T_B       TILE_SZ
#define STAGE_SZ  (2 * TILE_SZ)    // 20480B
#define NSTAGE    3
#define GEMM_SMEM (NSTAGE * STAGE_SZ)  // 61440B

__global__ __launch_bounds__(128, 2) void gemm_mma_kernel()
{
    extern __shared__ char smem[];
    const uint32_t sb = smem_u32(smem);
    const int tid = threadIdx.x;
    const int wid = tid >> 5;
    const int lane = tid & 31;
    const int warp_m = wid >> 1;          // 0..1
    const int warp_n = wid & 1;           // 0..1
    const int b     = blockIdx.z;
    const int mBase = blockIdx.x * 128;   // m fastest for B-tile L2 reuse
    const int nBase = blockIdx.y * 128;

    const __half* wB = g_wh + (size_t)mBase * CC;
    const __half* xB = g_xh + ((size_t)b * NPIX + nBase) * CC;

    // Loader: thread tid loads row=tid, segs 0..3, for both A and B.
    const uint32_t sm_row = (uint32_t)(tid * ROWB);
    const size_t   gm_row = (size_t)tid * CC;

    auto stage = [&](int c) {
        const uint32_t bufS = sb + (uint32_t)((c % NSTAGE) * STAGE_SZ);
        const int kc = c * KC;
        #pragma unroll
        for (int seg = 0; seg < 4; seg++) {
            const uint32_t so = sm_row + seg * 16;
            const size_t   go = gm_row + seg * 8 + kc;
            cp_async16(bufS + T_A + so, wB + go);
            cp_async16(bufS + T_B + so, xB + go);
        }
        cp_commit();
    };

    float acc[4][8][4];
    #pragma unroll
    for (int mt = 0; mt < 4; mt++)
        #pragma unroll
        for (int nt = 0; nt < 8; nt++)
            #pragma unroll
            for (int r = 0; r < 4; r++) acc[mt][nt][r] = 0.f;

    stage(0);
    stage(1);

    const uint32_t aRow = (uint32_t)(warp_m * 64 + (lane & 15));
    const uint32_t aByt = (uint32_t)((lane >> 4) * 16);
    const uint32_t bRow = (uint32_t)(warp_n * 64 + ((lane >> 4) << 3) + (lane & 7));
    const uint32_t bByt = (uint32_t)(((lane >> 3) & 1) * 16);

    const int NCH = CC / KC;   // 16
    for (int c = 0; c < NCH; c++) {
        if (c + 2 < NCH) { stage(c + 2); cp_wait<2>(); }
        else if (c + 1 < NCH) { cp_wait<1>(); }
        else { cp_wait<0>(); }
        __syncthreads();

        const uint32_t bufS = sb + (uint32_t)((c % NSTAGE) * STAGE_SZ);

        #pragma unroll
        for (int ks = 0; ks < 2; ks++) {
            const uint32_t kOff = (uint32_t)(ks * 32);
            uint32_t af[4][4];
            #pragma unroll
            for (int mt = 0; mt < 4; mt++) {
                const uint32_t ao = (aRow + mt * 16) * ROWB + kOff + aByt;
                ldsm_x4(af[mt][0], af[mt][1], af[mt][2], af[mt][3],
                        bufS + T_A + ao);
            }
            #pragma unroll
            for (int np = 0; np < 4; np++) {
                const uint32_t bo = (bRow + np * 16) * ROWB + kOff + bByt;
                uint32_t bf[4];
                ldsm_x4(bf[0], bf[1], bf[2], bf[3], bufS + T_B + bo);
                #pragma unroll
                for (int mt = 0; mt < 4; mt++) {
                    #pragma unroll
                    for (int j = 0; j < 2; j++)
                        mma_fp16(acc[mt][np * 2 + j], af[mt], bf + 2 * j);
                }
            }
        }
        __syncthreads();
    }

    // Epilogue: fp16 packed-quad stores. Thread owns rows rr0+16*mt+{0,8}:
    // mt 0-1 -> quad at rows rr0..rr0+24, mt 2-3 -> quad at rows rr0+32..+56.
    const int rr0  = mBase + warp_m * 64 + (lane >> 2);   // (rr0 & 31) < 8
    const int qidxA = ((rr0 >> 5) << 3) | (rr0 & 7);
    const int qidxB = qidxA + 8;                          // rows +32
    __half* qbA = g_qh + ((size_t)b * NQ + qidxA) * ((size_t)NPIX * 4);
    __half* qbB = g_qh + ((size_t)b * NQ + qidxB) * ((size_t)NPIX * 4);
    const int cc0 = nBase + warp_n * 64 + (lane & 3) * 2;
    #pragma unroll
    for (int nt = 0; nt < 8; nt++) {
        const int cc = cc0 + nt * 8;
        {   // quad A (mt 0,1)
            __half2 h0 = __float22half2_rn(make_float2(acc[0][nt][0], acc[0][nt][2]));
            __half2 h1 = __float22half2_rn(make_float2(acc[1][nt][0], acc[1][nt][2]));
            __half2 h2 = __float22half2_rn(make_float2(acc[0][nt][1], acc[0][nt][3]));
            __half2 h3 = __float22half2_rn(make_float2(acc[1][nt][1], acc[1][nt][3]));
            uint4 u = make_uint4(h2bits(h0), h2bits(h1), h2bits(h2), h2bits(h3));
            *reinterpret_cast<uint4*>(qbA + (size_t)cc * 4) = u;
        }
        {   // quad B (mt 2,3)
            __half2 h0 = __float22half2_rn(make_float2(acc[2][nt][0], acc[2][nt][2]));
            __half2 h1 = __float22half2_rn(make_float2(acc[3][nt][0], acc[3][nt][2]));
            __half2 h2 = __float22half2_rn(make_float2(acc[2][nt][1], acc[2][nt][3]));
            __half2 h3 = __float22half2_rn(make_float2(acc[3][nt][1], acc[3][nt][3]));
            uint4 u = make_uint4(h2bits(h0), h2bits(h1), h2bits(h2), h2bits(h3));
            *reinterpret_cast<uint4*>(qbB + (size_t)cc * 4) = u;
        }
    }
}

// ---------------------------------------------------------------------------
// Gate: one block per batch
// ---------------------------------------------------------------------------
__global__ __launch_bounds__(256) void gate_kernel(
    const float* __restrict__ w_gate, const float* __restrict__ b_gate)
{
    const int b = blockIdx.x;
    const int tid = threadIdx.x;
    const int lane = tid & 31;
    const int warp = tid >> 5;

    float s[ND] = {0.f, 0.f, 0.f, 0.f};
    for (int c = tid; c < CC; c += 256) {
        float p = g_pooled[b * CC + c] * (1.0f / NPIX);
        #pragma unroll
        for (int i = 0; i < ND; i++) s[i] += p * w_gate[i * CC + c];
    }
    #pragma unroll
    for (int i = 0; i < ND; i++)
        #pragma unroll
        for (int off = 16; off > 0; off >>= 1)
            s[i] += __shfl_xor_sync(0xFFFFFFFFu, s[i], off);

    __shared__ float sred[8][ND];
    if (lane == 0)
        #pragma unroll
        for (int i = 0; i < ND; i++) sred[warp][i] = s[i];
    __syncthreads();
    if (tid == 0) {
        float logits[ND];
        float m = -1e30f;
        #pragma unroll
        for (int i = 0; i < ND; i++) {
            float t = b_gate[i];
            #pragma unroll
            for (int wdx = 0; wdx < 8; wdx++) t += sred[wdx][i];
            logits[i] = t;
            m = fmaxf(m, t);
        }
        float den = 0.f;
        #pragma unroll
        for (int i = 0; i < ND; i++) { logits[i] = __expf(logits[i] - m); den += logits[i]; }
        float inv = 1.f / den;
        #pragma unroll
        for (int i = 0; i < ND; i++) g_gate[b * ND + i] = logits[i] * inv;
    }
}

// ---------------------------------------------------------------------------
// Dilated 3x3 attention + gate, fp16 packed-quad loads (uint2 = 4 channels)
// ---------------------------------------------------------------------------
__global__ __launch_bounds__(128) void attn_kernel(float* __restrict__ out)
{
    const int n  = blockIdx.x * 128 + threadIdx.x;
    const int bh = blockIdx.y;
    const int b  = blockIdx.z;
    const int branch = bh >> 1;
    const int dil    = 1 << branch;
    const int qc     = branch * BD + (bh & 1) * HD;   // multiple of 64

    const int qidx0 = (qc >> 5) << 3;
    const __half* qp = g_qh + ((size_t)b * NQ + qidx0) * ((size_t)NPIX * 4);
    const __half* kp = qp + (size_t)(CC / 4) * NPIX * 4;
    const __half* vp = qp + (size_t)(2 * (CC / 4)) * NPIX * 4;

    const int y  = n >> 6;
    const int xx = n & 63;

    int n2s[9];
    float sc[9];
    #pragma unroll
    for (int p = 0; p < 9; p++) {
        const int y2 = y + (p / 3 - 1) * dil;
        const int x2 = xx + (p % 3 - 1) * dil;
        const bool ok = ((unsigned)y2 < 64u) && ((unsigned)x2 < 64u);
        n2s[p] = ok ? y2 * 64 + x2 : -1;
        sc[p] = 0.f;
    }

    #pragma unroll
    for (int th = 0; th < 2; th++) {
        float qf[32];
        #pragma unroll
        for (int t = 0; t < 8; t++) {
            uint2 u = *reinterpret_cast<const uint2*>(
                qp + ((size_t)(th * 8 + t) * NPIX + n) * 4);
            float2 a = __half22float2(*reinterpret_cast<__half2*>(&u.x));
            float2 c = __half22float2(*reinterpret_cast<__half2*>(&u.y));
            qf[t * 4 + 0] = a.x; qf[t * 4 + 1] = a.y;
            qf[t * 4 + 2] = c.x; qf[t * 4 + 3] = c.y;
        }
        #pragma unroll
        for (int p = 0; p < 9; p++) {
            if (n2s[p] >= 0) {
                float s = 0.f;
                #pragma unroll
                for (int t = 0; t < 8; t++) {
                    uint2 u = *reinterpret_cast<const uint2*>(
                        kp + ((size_t)(th * 8 + t) * NPIX + n2s[p]) * 4);
                    float2 a = __half22float2(*reinterpret_cast<__half2*>(&u.x));
                    float2 c = __half22float2(*reinterpret_cast<__half2*>(&u.y));
                    s = fmaf(qf[t * 4 + 0], a.x, s);
                    s = fmaf(qf[t * 4 + 1], a.y, s);
                    s = fmaf(qf[t * 4 + 2], c.x, s);
                    s = fmaf(qf[t * 4 + 3], c.y, s);
                }
                sc[p] += s;
            }
        }
    }
    #pragma unroll
    for (int p = 0; p < 9; p++) sc[p] *= 0.125f;

    float m = sc[0];
    #pragma unroll
    for (int p = 1; p < 9; p++) m = fmaxf(m, sc[p]);
    float den = 0.f;
    #pragma unroll
    for (int p = 0; p < 9; p++) { sc[p] = __expf(sc[p] - m); den += sc[p]; }
    const float inv = 1.f / den;
    #pragma unroll
    for (int p = 0; p < 9; p++) sc[p] *= inv;

    const float g = g_gate[b * ND + branch];
    float* op = out + ((size_t)b * CC + qc) * NPIX + n;

    #pragma unroll
    for (int th = 0; th < 2; th++) {
        float o[32];
        #pragma unroll
        for (int i = 0; i < 32; i++) o[i] = 0.f;
        #pragma unroll
        for (int p = 0; p < 9; p++) {
            if (n2s[p] >= 0) {
                const float wgt = sc[p];
                #pragma unroll
                for (int t = 0; t < 8; t++) {
                    uint2 u = *reinterpret_cast<const uint2*>(
                        vp + ((size_t)(th * 8 + t) * NPIX + n2s[p]) * 4);
                    float2 a = __half22float2(*reinterpret_cast<__half2*>(&u.x));
                    float2 c = __half22float2(*reinterpret_cast<__half2*>(&u.y));
                    o[t * 4 + 0] = fmaf(wgt, a.x, o[t * 4 + 0]);
                    o[t * 4 + 1] = fmaf(wgt, a.y, o[t * 4 + 1]);
                    o[t * 4 + 2] = fmaf(wgt, c.x, o[t * 4 + 2]);
                    o[t * 4 + 3] = fmaf(wgt, c.y, o[t * 4 + 3]);
                }
            }
        }
        #pragma unroll
        for (int t = 0; t < 8; t++)
            #pragma unroll
            for (int s = 0; s < 4; s++) {
                const int d = th * 32 + t + s * 8;
                op[(size_t)d * NPIX] = o[t * 4 + s] * g;
            }
    }
}

// ---------------------------------------------------------------------------
// Launch
// ---------------------------------------------------------------------------
extern "C" void kernel_launch(void* const* d_in, const int* in_sizes, int n_in,
                              void* d_out, int out_size)
{
    (void)in_sizes; (void)n_in; (void)out_size;
    const float* x      = (const float*)d_in[0];  // (8, 512, 64, 64)
    const float* w_qkv  = (const float*)d_in[1];  // (1536, 512)
    const float* w_gate = (const float*)d_in[2];  // (4, 512)
    const float* b_gate = (const float*)d_in[3];  // (4,)
    float* out = (float*)d_out;                   // (8, 512, 64, 64)

    cudaFuncSetAttribute(gemm_mma_kernel,
                         cudaFuncAttributeMaxDynamicSharedMemorySize, GEMM_SMEM);

    split_w_kernel<<<(OC * CC) / 256, 256>>>(w_qkv);          // + pooled zeroing
    tsx_kernel<<<dim3(NPIX / 32, CC / 32, BB), dim3(32, 8)>>>(x);
    gate_kernel<<<BB, 256>>>(w_gate, b_gate);

    gemm_mma_kernel<<<dim3(OC / 128, NPIX / 128, BB), 128, GEMM_SMEM>>>();

    attn_kernel<<<dim3(NPIX / 128, 2 * ND, BB), 128>>>(out);
}

// round 10
// speedup vs baseline: 1.1466x; 1.1466x over previous
#include <cuda_runtime.h>
#include <cuda_fp16.h>
#include <cstdint>

// Problem constants
#define BB   8
#define CC   512
#define NPIX 4096
#define OC   1536
#define NQ   (OC / 4)      // quad-channel groups = 384
#define ND   4
#define BD   128
#define HD   64

// Scratch (static device allocations — allowed)
// Packed-quad fp16 qkv: layout [b][qidx][n][4], qidx = (c>>5)*8 + (c&7),
// sub = (c>>3)&3 → pixel n holds channels (c0, c0+8, c0+16, c0+24).
__device__ __align__(16) __half g_qh[(size_t)BB * OC * NPIX];   // 96 MB
__device__ float g_pooled[BB * CC];
__device__ float g_gate[BB * ND];
__device__ __align__(16) __half g_wh[OC * CC];                  // fp16 w
__device__ __align__(16) __half g_xh[(size_t)BB * NPIX * CC];   // fp16 x, [b][n][c]

// ---------------------------------------------------------------------------
// PTX helpers (sm_80+ only)
// ---------------------------------------------------------------------------
__device__ __forceinline__ uint32_t smem_u32(const void* p) {
    uint32_t a;
    asm("{ .reg .u64 t; cvta.to.shared.u64 t, %1; cvt.u32.u64 %0, t; }"
        : "=r"(a) : "l"(p));
    return a;
}
__device__ __forceinline__ void cp_async16(uint32_t s, const void* g) {
    asm volatile("cp.async.cg.shared.global [%0], [%1], 16;" :: "r"(s), "l"(g));
}
__device__ __forceinline__ void cp_commit() {
    asm volatile("cp.async.commit_group;" ::: "memory");
}
template <int N>
__device__ __forceinline__ void cp_wait() {
    asm volatile("cp.async.wait_group %0;" :: "n"(N) : "memory");
}
__device__ __forceinline__ void ldsm_x4(uint32_t& r0, uint32_t& r1,
                                        uint32_t& r2, uint32_t& r3, uint32_t a) {
    asm volatile("ldmatrix.sync.aligned.m8n8.x4.shared.b16 {%0,%1,%2,%3}, [%4];"
                 : "=r"(r0), "=r"(r1), "=r"(r2), "=r"(r3) : "r"(a));
}
__device__ __forceinline__ void mma_fp16(float* d, const uint32_t* a, const uint32_t* b) {
    asm volatile("mma.sync.aligned.m16n8k16.row.col.f32.f16.f16.f32 "
                 "{%0,%1,%2,%3}, {%4,%5,%6,%7}, {%8,%9}, {%0,%1,%2,%3};"
                 : "+f"(d[0]), "+f"(d[1]), "+f"(d[2]), "+f"(d[3])
                 : "r"(a[0]), "r"(a[1]), "r"(a[2]), "r"(a[3]),
                   "r"(b[0]), "r"(b[1]));
}
__device__ __forceinline__ uint32_t h2bits(__half2 h) {
    return *reinterpret_cast<uint32_t*>(&h);
}

// ---------------------------------------------------------------------------
// Pre-pass 1: w -> fp16, fused zeroing of the pooled accumulator
// ---------------------------------------------------------------------------
__global__ __launch_bounds__(256) void split_w_kernel(const float* __restrict__ w)
{
    int i = blockIdx.x * 256 + threadIdx.x;
    g_wh[i] = __float2half(w[i]);
    if (i < BB * CC) g_pooled[i] = 0.f;
}

// ---------------------------------------------------------------------------
// Pre-pass 2: transpose x [b][c][n] -> [b][n][c] as fp16, fused mean-pool
// partial sums (atomicAdd raw sums; gate divides by NPIX).
// ---------------------------------------------------------------------------
__global__ __launch_bounds__(256) void tsx_kernel(const float* __restrict__ x)
{
    __shared__ float t[32][33];
    const int b  = blockIdx.z;
    const int n0 = blockIdx.x * 32;
    const int c0 = blockIdx.y * 32;
    const int tx = threadIdx.x, ty = threadIdx.y;

    #pragma unroll
    for (int i = ty; i < 32; i += 8)
        t[i][tx] = x[((size_t)b * CC + c0 + i) * NPIX + n0 + tx];
    __syncthreads();

    float psum = 0.f;
    #pragma unroll
    for (int i = ty; i < 32; i += 8) {
        float v = t[tx][i];   // x[c0+tx][n0+i]
        psum += v;
        g_xh[((size_t)b * NPIX + n0 + i) * CC + c0 + tx] = __float2half(v);
    }
    __syncthreads();
    t[ty][tx] = psum;
    __syncthreads();
    if (ty == 0) {
        float s = 0.f;
        #pragma unroll
        for (int j = 0; j < 8; j++) s += t[j][tx];
        atomicAdd(&g_pooled[b * CC + c0 + tx], s);
    }
}

// ---------------------------------------------------------------------------
// fp16 GEMM via mma.sync: qkv[b][o][n] = sum_c w[o][c] x[b][c][n]
// 128x128 CTA tile, 8 warps (4m x 2n), warp tile 32x64 (R6 layout),
// K chunk 64, double-buffered cp.async. Epilogue: fp16 packed-quad stores.
// ---------------------------------------------------------------------------
#define KC        64
#define ROWB      144              // 64 fp16 = 128B + 16B pad (banks 4r mod 32)
#define TILE_SZ   (128 * ROWB)     // 18432B
#define T_A       0
#define T_B       TILE_SZ
#define STAGE_SZ  (2 * TILE_SZ)    // 36864B
#define GEMM_SMEM (2 * STAGE_SZ)   // 73728B

__global__ __launch_bounds__(256, 2) void gemm_mma_kernel()
{
    extern __shared__ char smem[];
    const uint32_t sb = smem_u32(smem);
    const int tid = threadIdx.x;
    const int wid = tid >> 5;
    const int lane = tid & 31;
    const int warp_m = wid >> 1;          // 0..3
    const int warp_n = wid & 1;           // 0..1
    const int b     = blockIdx.z;
    const int mBase = blockIdx.x * 128;   // m fastest for B-tile L2 reuse
    const int nBase = blockIdx.y * 128;

    const __half* wB = g_wh + (size_t)mBase * CC;
    const __half* xB = g_xh + ((size_t)b * NPIX + nBase) * CC;

    // Loader: 1024 16B-units per tile (128 rows x 8 segs); thread handles
    // row = tid>>1, segs (tid&1)*4 .. +3, for both A and B (8 cp.async/stage).
    const int lrow = tid >> 1;
    const int lseg = (tid & 1) * 4;
    const uint32_t sm_off0 = (uint32_t)(lrow * ROWB + lseg * 16);
    const size_t   gm_off0 = (size_t)lrow * CC + lseg * 8;

    auto stage = [&](int c) {
        const uint32_t bufS = sb + (uint32_t)((c & 1) * STAGE_SZ);
        const int kc = c * KC;
        #pragma unroll
        for (int i = 0; i < 4; i++) {
            const uint32_t so = sm_off0 + i * 16;
            const size_t   go = gm_off0 + i * 8 + kc;
            cp_async16(bufS + T_A + so, wB + go);
            cp_async16(bufS + T_B + so, xB + go);
        }
        cp_commit();
    };

    float acc[2][8][4];
    #pragma unroll
    for (int mt = 0; mt < 2; mt++)
        #pragma unroll
        for (int nt = 0; nt < 8; nt++)
            #pragma unroll
            for (int r = 0; r < 4; r++) acc[mt][nt][r] = 0.f;

    stage(0);

    const uint32_t aRow = (uint32_t)(warp_m * 32 + (lane & 15));
    const uint32_t aByt = (uint32_t)((lane >> 4) * 16);
    const uint32_t bRow = (uint32_t)(warp_n * 64 + ((lane >> 4) << 3) + (lane & 7));
    const uint32_t bByt = (uint32_t)(((lane >> 3) & 1) * 16);

    const int NCH = CC / KC;   // 8
    for (int c = 0; c < NCH; c++) {
        if (c + 1 < NCH) { stage(c + 1); cp_wait<1>(); }
        else             { cp_wait<0>(); }
        __syncthreads();

        const uint32_t bufS = sb + (uint32_t)((c & 1) * STAGE_SZ);

        #pragma unroll
        for (int ks = 0; ks < 4; ks++) {
            const uint32_t kOff = (uint32_t)(ks * 32);
            uint32_t af[2][4];
            #pragma unroll
            for (int mt = 0; mt < 2; mt++) {
                const uint32_t ao = (aRow + mt * 16) * ROWB + kOff + aByt;
                ldsm_x4(af[mt][0], af[mt][1], af[mt][2], af[mt][3],
                        bufS + T_A + ao);
            }
            #pragma unroll
            for (int np = 0; np < 4; np++) {
                const uint32_t bo = (bRow + np * 16) * ROWB + kOff + bByt;
                uint32_t bf[4];
                ldsm_x4(bf[0], bf[1], bf[2], bf[3], bufS + T_B + bo);
                #pragma unroll
                for (int mt = 0; mt < 2; mt++) {
                    #pragma unroll
                    for (int j = 0; j < 2; j++)
                        mma_fp16(acc[mt][np * 2 + j], af[mt], bf + 2 * j);
                }
            }
        }
        __syncthreads();
    }

    // Epilogue: fp16 packed-quad stores. Thread owns rows rr0, rr0+8 (mt 0)
    // and rr0+16, rr0+24 (mt 1) — exactly one channel-quad.
    const int rr0  = mBase + warp_m * 32 + (lane >> 2);   // (rr0 & 31) < 8
    const int qidx = ((rr0 >> 5) << 3) | (rr0 & 7);
    __half* qb = g_qh + ((size_t)b * NQ + qidx) * ((size_t)NPIX * 4);
    const int cc0 = nBase + warp_n * 64 + (lane & 3) * 2;
    #pragma unroll
    for (int nt = 0; nt < 8; nt++) {
        const int cc = cc0 + nt * 8;
        __half2 h0 = __float22half2_rn(make_float2(acc[0][nt][0], acc[0][nt][2]));
        __half2 h1 = __float22half2_rn(make_float2(acc[1][nt][0], acc[1][nt][2]));
        __half2 h2 = __float22half2_rn(make_float2(acc[0][nt][1], acc[0][nt][3]));
        __half2 h3 = __float22half2_rn(make_float2(acc[1][nt][1], acc[1][nt][3]));
        uint4 u = make_uint4(h2bits(h0), h2bits(h1), h2bits(h2), h2bits(h3));
        *reinterpret_cast<uint4*>(qb + (size_t)cc * 4) = u;
    }
}

// ---------------------------------------------------------------------------
// Gate: one block per batch
// ---------------------------------------------------------------------------
__global__ __launch_bounds__(256) void gate_kernel(
    const float* __restrict__ w_gate, const float* __restrict__ b_gate)
{
    const int b = blockIdx.x;
    const int tid = threadIdx.x;
    const int lane = tid & 31;
    const int warp = tid >> 5;

    float s[ND] = {0.f, 0.f, 0.f, 0.f};
    for (int c = tid; c < CC; c += 256) {
        float p = g_pooled[b * CC + c] * (1.0f / NPIX);
        #pragma unroll
        for (int i = 0; i < ND; i++) s[i] += p * w_gate[i * CC + c];
    }
    #pragma unroll
    for (int i = 0; i < ND; i++)
        #pragma unroll
        for (int off = 16; off > 0; off >>= 1)
            s[i] += __shfl_xor_sync(0xFFFFFFFFu, s[i], off);

    __shared__ float sred[8][ND];
    if (lane == 0)
        #pragma unroll
        for (int i = 0; i < ND; i++) sred[warp][i] = s[i];
    __syncthreads();
    if (tid == 0) {
        float logits[ND];
        float m = -1e30f;
        #pragma unroll
        for (int i = 0; i < ND; i++) {
            float t = b_gate[i];
            #pragma unroll
            for (int wdx = 0; wdx < 8; wdx++) t += sred[wdx][i];
            logits[i] = t;
            m = fmaxf(m, t);
        }
        float den = 0.f;
        #pragma unroll
        for (int i = 0; i < ND; i++) { logits[i] = __expf(logits[i] - m); den += logits[i]; }
        float inv = 1.f / den;
        #pragma unroll
        for (int i = 0; i < ND; i++) g_gate[b * ND + i] = logits[i] * inv;
    }
}

// ---------------------------------------------------------------------------
// Dilated 3x3 attention + gate, fp16 packed-quad loads (uint2 = 4 channels)
// ---------------------------------------------------------------------------
__global__ __launch_bounds__(128) void attn_kernel(float* __restrict__ out)
{
    const int n  = blockIdx.x * 128 + threadIdx.x;
    const int bh = blockIdx.y;
    const int b  = blockIdx.z;
    const int branch = bh >> 1;
    const int dil    = 1 << branch;
    const int qc     = branch * BD + (bh & 1) * HD;   // multiple of 64

    const int qidx0 = (qc >> 5) << 3;
    const __half* qp = g_qh + ((size_t)b * NQ + qidx0) * ((size_t)NPIX * 4);
    const __half* kp = qp + (size_t)(CC / 4) * NPIX * 4;
    const __half* vp = qp + (size_t)(2 * (CC / 4)) * NPIX * 4;

    const int y  = n >> 6;
    const int xx = n & 63;

    int n2s[9];
    float sc[9];
    #pragma unroll
    for (int p = 0; p < 9; p++) {
        const int y2 = y + (p / 3 - 1) * dil;
        const int x2 = xx + (p % 3 - 1) * dil;
        const bool ok = ((unsigned)y2 < 64u) && ((unsigned)x2 < 64u);
        n2s[p] = ok ? y2 * 64 + x2 : -1;
        sc[p] = 0.f;
    }

    #pragma unroll
    for (int th = 0; th < 2; th++) {
        float qf[32];
        #pragma unroll
        for (int t = 0; t < 8; t++) {
            uint2 u = *reinterpret_cast<const uint2*>(
                qp + ((size_t)(th * 8 + t) * NPIX + n) * 4);
            float2 a = __half22float2(*reinterpret_cast<__half2*>(&u.x));
            float2 c = __half22float2(*reinterpret_cast<__half2*>(&u.y));
            qf[t * 4 + 0] = a.x; qf[t * 4 + 1] = a.y;
            qf[t * 4 + 2] = c.x; qf[t * 4 + 3] = c.y;
        }
        #pragma unroll
        for (int p = 0; p < 9; p++) {
            if (n2s[p] >= 0) {
                float s = 0.f;
                #pragma unroll
                for (int t = 0; t < 8; t++) {
                    uint2 u = *reinterpret_cast<const uint2*>(
                        kp + ((size_t)(th * 8 + t) * NPIX + n2s[p]) * 4);
                    float2 a = __half22float2(*reinterpret_cast<__half2*>(&u.x));
                    float2 c = __half22float2(*reinterpret_cast<__half2*>(&u.y));
                    s = fmaf(qf[t * 4 + 0], a.x, s);
                    s = fmaf(qf[t * 4 + 1], a.y, s);
                    s = fmaf(qf[t * 4 + 2], c.x, s);
                    s = fmaf(qf[t * 4 + 3], c.y, s);
                }
                sc[p] += s;
            }
        }
    }
    #pragma unroll
    for (int p = 0; p < 9; p++) sc[p] *= 0.125f;

    float m = sc[0];
    #pragma unroll
    for (int p = 1; p < 9; p++) m = fmaxf(m, sc[p]);
    float den = 0.f;
    #pragma unroll
    for (int p = 0; p < 9; p++) { sc[p] = __expf(sc[p] - m); den += sc[p]; }
    const float inv = 1.f / den;
    #pragma unroll
    for (int p = 0; p < 9; p++) sc[p] *= inv;

    const float g = g_gate[b * ND + branch];
    float* op = out + ((size_t)b * CC + qc) * NPIX + n;

    #pragma unroll
    for (int th = 0; th < 2; th++) {
        float o[32];
        #pragma unroll
        for (int i = 0; i < 32; i++) o[i] = 0.f;
        #pragma unroll
        for (int p = 0; p < 9; p++) {
            if (n2s[p] >= 0) {
                const float wgt = sc[p];
                #pragma unroll
                for (int t = 0; t < 8; t++) {
                    uint2 u = *reinterpret_cast<const uint2*>(
                        vp + ((size_t)(th * 8 + t) * NPIX + n2s[p]) * 4);
                    float2 a = __half22float2(*reinterpret_cast<__half2*>(&u.x));
                    float2 c = __half22float2(*reinterpret_cast<__half2*>(&u.y));
                    o[t * 4 + 0] = fmaf(wgt, a.x, o[t * 4 + 0]);
                    o[t * 4 + 1] = fmaf(wgt, a.y, o[t * 4 + 1]);
                    o[t * 4 + 2] = fmaf(wgt, c.x, o[t * 4 + 2]);
                    o[t * 4 + 3] = fmaf(wgt, c.y, o[t * 4 + 3]);
                }
            }
        }
        #pragma unroll
        for (int t = 0; t < 8; t++)
            #pragma unroll
            for (int s = 0; s < 4; s++) {
                const int d = th * 32 + t + s * 8;
                op[(size_t)d * NPIX] = o[t * 4 + s] * g;
            }
    }
}

// ---------------------------------------------------------------------------
// Launch
// ---------------------------------------------------------------------------
extern "C" void kernel_launch(void* const* d_in, const int* in_sizes, int n_in,
                              void* d_out, int out_size)
{
    (void)in_sizes; (void)n_in; (void)out_size;
    const float* x      = (const float*)d_in[0];  // (8, 512, 64, 64)
    const float* w_qkv  = (const float*)d_in[1];  // (1536, 512)
    const float* w_gate = (const float*)d_in[2];  // (4, 512)
    const float* b_gate = (const float*)d_in[3];  // (4,)
    float* out = (float*)d_out;                   // (8, 512, 64, 64)

    cudaFuncSetAttribute(gemm_mma_kernel,
                         cudaFuncAttributeMaxDynamicSharedMemorySize, GEMM_SMEM);

    split_w_kernel<<<(OC * CC) / 256, 256>>>(w_qkv);          // + pooled zeroing
    tsx_kernel<<<dim3(NPIX / 32, CC / 32, BB), dim3(32, 8)>>>(x);
    gate_kernel<<<BB, 256>>>(w_gate, b_gate);

    gemm_mma_kernel<<<dim3(OC / 128, NPIX / 128, BB), 256, GEMM_SMEM>>>();

    attn_kernel<<<dim3(NPIX / 128, 2 * ND, BB), 128>>>(out);
}

// round 12
// speedup vs baseline: 1.2875x; 1.1230x over previous
#include <cuda_runtime.h>
#include <cuda_fp16.h>
#include <cstdint>

// Problem constants
#define BB   8
#define CC   512
#define NPIX 4096
#define OC   1536
#define NQ   (OC / 4)      // quad-channel groups = 384
#define ND   4
#define BD   128
#define HD   64

// Scratch (static device allocations — allowed)
// Packed-quad fp16 qkv: layout [b][qidx][n][4], qidx = (c>>5)*8 + (c&7),
// sub = (c>>3)&3 → pixel n holds channels (c0, c0+8, c0+16, c0+24).
__device__ __align__(16) __half g_qh[(size_t)BB * OC * NPIX];   // 96 MB
__device__ float g_pooled[BB * CC];
__device__ float g_gate[BB * ND];
__device__ __align__(16) __half g_wh[OC * CC];                  // fp16 w
__device__ __align__(16) __half g_xh[(size_t)BB * NPIX * CC];   // fp16 x, [b][n][c]

// ---------------------------------------------------------------------------
// PTX helpers (sm_80+ only)
// ---------------------------------------------------------------------------
__device__ __forceinline__ uint32_t smem_u32(const void* p) {
    uint32_t a;
    asm("{ .reg .u64 t; cvta.to.shared.u64 t, %1; cvt.u32.u64 %0, t; }"
        : "=r"(a) : "l"(p));
    return a;
}
__device__ __forceinline__ void cp_async16(uint32_t s, const void* g) {
    asm volatile("cp.async.cg.shared.global [%0], [%1], 16;" :: "r"(s), "l"(g));
}
__device__ __forceinline__ void cp_commit() {
    asm volatile("cp.async.commit_group;" ::: "memory");
}
template <int N>
__device__ __forceinline__ void cp_wait() {
    asm volatile("cp.async.wait_group %0;" :: "n"(N) : "memory");
}
__device__ __forceinline__ void ldsm_x4(uint32_t& r0, uint32_t& r1,
                                        uint32_t& r2, uint32_t& r3, uint32_t a) {
    asm volatile("ldmatrix.sync.aligned.m8n8.x4.shared.b16 {%0,%1,%2,%3}, [%4];"
                 : "=r"(r0), "=r"(r1), "=r"(r2), "=r"(r3) : "r"(a));
}
__device__ __forceinline__ void mma_fp16(float* d, const uint32_t* a, const uint32_t* b) {
    asm volatile("mma.sync.aligned.m16n8k16.row.col.f32.f16.f16.f32 "
                 "{%0,%1,%2,%3}, {%4,%5,%6,%7}, {%8,%9}, {%0,%1,%2,%3};"
                 : "+f"(d[0]), "+f"(d[1]), "+f"(d[2]), "+f"(d[3])
                 : "r"(a[0]), "r"(a[1]), "r"(a[2]), "r"(a[3]),
                   "r"(b[0]), "r"(b[1]));
}
__device__ __forceinline__ uint32_t h2bits(__half2 h) {
    return *reinterpret_cast<uint32_t*>(&h);
}

// ---------------------------------------------------------------------------
// Pre-pass 1: w -> fp16, fused zeroing of the pooled accumulator
// ---------------------------------------------------------------------------
__global__ __launch_bounds__(256) void split_w_kernel(const float* __restrict__ w)
{
    int i = blockIdx.x * 256 + threadIdx.x;
    g_wh[i] = __float2half(w[i]);
    if (i < BB * CC) g_pooled[i] = 0.f;
}

// ---------------------------------------------------------------------------
// Pre-pass 2: transpose x [b][c][n] -> [b][n][c] as fp16, fused mean-pool
// partial sums (atomicAdd raw sums; gate divides by NPIX).
// ---------------------------------------------------------------------------
__global__ __launch_bounds__(256) void tsx_kernel(const float* __restrict__ x)
{
    __shared__ float t[32][33];
    const int b  = blockIdx.z;
    const int n0 = blockIdx.x * 32;
    const int c0 = blockIdx.y * 32;
    const int tx = threadIdx.x, ty = threadIdx.y;

    #pragma unroll
    for (int i = ty; i < 32; i += 8)
        t[i][tx] = x[((size_t)b * CC + c0 + i) * NPIX + n0 + tx];
    __syncthreads();

    float psum = 0.f;
    #pragma unroll
    for (int i = ty; i < 32; i += 8) {
        float v = t[tx][i];   // x[c0+tx][n0+i]
        psum += v;
        g_xh[((size_t)b * NPIX + n0 + i) * CC + c0 + tx] = __float2half(v);
    }
    __syncthreads();
    t[ty][tx] = psum;
    __syncthreads();
    if (ty == 0) {
        float s = 0.f;
        #pragma unroll
        for (int j = 0; j < 8; j++) s += t[j][tx];
        atomicAdd(&g_pooled[b * CC + c0 + tx], s);
    }
}

// ---------------------------------------------------------------------------
// fp16 GEMM via mma.sync: qkv[b][o][n] = sum_c w[o][c] x[b][c][n]
// 128x128 CTA tile, 8 warps (4m x 2n), warp tile 32x64 (R6 layout), K chunk 32,
// 4-stage cp.async ring with lookahead 2 and ONE barrier per chunk.
// Epilogue: fp16 packed-quad stores.
// ---------------------------------------------------------------------------
#define KC        32
#define ROWB      80               // 32 fp16 = 64B + 16B pad
#define TILE_SZ   (128 * ROWB)     // 10240B
#define T_A       0
#define T_B       TILE_SZ
#define STAGE_SZ  (2 * TILE_SZ)    // 20480B
#define NSTAGE    4
#define GEMM_SMEM (NSTAGE * STAGE_SZ)  // 81920B

__global__ __launch_bounds__(256, 2) void gemm_mma_kernel()
{
    extern __shared__ char smem[];
    const uint32_t sb = smem_u32(smem);
    const int tid = threadIdx.x;
    const int wid = tid >> 5;
    const int lane = tid & 31;
    const int warp_m = wid >> 1;          // 0..3
    const int warp_n = wid & 1;           // 0..1
    const int b     = blockIdx.z;
    const int mBase = blockIdx.x * 128;   // m fastest for B-tile L2 reuse
    const int nBase = blockIdx.y * 128;

    const __half* wB = g_wh + (size_t)mBase * CC;
    const __half* xB = g_xh + ((size_t)b * NPIX + nBase) * CC;

    // Loader: 512 16B-units per tile; each thread: 2 units A + 2 units B.
    const int u0   = tid * 2;
    const int row0 = u0 >> 2;             // 0..127
    const int seg0 = u0 & 3;              // 0 or 2
    const uint32_t sm_off0 = (uint32_t)(row0 * ROWB + seg0 * 16);
    const size_t   gm_off0 = (size_t)row0 * CC + seg0 * 8;

    auto stage = [&](int c) {
        const uint32_t bufS = sb + (uint32_t)((c % NSTAGE) * STAGE_SZ);
        const int kc = c * KC;
        #pragma unroll
        for (int i = 0; i < 2; i++) {
            const uint32_t so = sm_off0 + i * 16;
            const size_t   go = gm_off0 + i * 8 + kc;
            cp_async16(bufS + T_A + so, wB + go);
            cp_async16(bufS + T_B + so, xB + go);
        }
        cp_commit();
    };

    float acc[2][8][4];
    #pragma unroll
    for (int mt = 0; mt < 2; mt++)
        #pragma unroll
        for (int nt = 0; nt < 8; nt++)
            #pragma unroll
            for (int r = 0; r < 4; r++) acc[mt][nt][r] = 0.f;

    stage(0);
    stage(1);

    const uint32_t aRow = (uint32_t)(warp_m * 32 + (lane & 15));
    const uint32_t aByt = (uint32_t)((lane >> 4) * 16);
    const uint32_t bRow = (uint32_t)(warp_n * 64 + ((lane >> 4) << 3) + (lane & 7));
    const uint32_t bByt = (uint32_t)(((lane >> 3) & 1) * 16);

    const int NCH = CC / KC;   // 16
    for (int c = 0; c < NCH; c++) {
        // Lookahead-2 prefetch into a 4-deep ring. stage(c+2) writes buffer
        // (c+2)%4 == (c-2)%4, whose readers (compute(c-2)) finished before
        // the sync at iteration c-1 — so no trailing barrier is needed.
        if (c + 2 < NCH) { stage(c + 2); cp_wait<2>(); }
        else if (c + 1 < NCH) { cp_wait<1>(); }
        else { cp_wait<0>(); }
        __syncthreads();   // single barrier per chunk

        const uint32_t bufS = sb + (uint32_t)((c % NSTAGE) * STAGE_SZ);

        #pragma unroll
        for (int ks = 0; ks < 2; ks++) {
            const uint32_t kOff = (uint32_t)(ks * 32);
            uint32_t af[2][4];
            #pragma unroll
            for (int mt = 0; mt < 2; mt++) {
                const uint32_t ao = (aRow + mt * 16) * ROWB + kOff + aByt;
                ldsm_x4(af[mt][0], af[mt][1], af[mt][2], af[mt][3],
                        bufS + T_A + ao);
            }
            #pragma unroll
            for (int np = 0; np < 4; np++) {
                const uint32_t bo = (bRow + np * 16) * ROWB + kOff + bByt;
                uint32_t bf[4];
                ldsm_x4(bf[0], bf[1], bf[2], bf[3], bufS + T_B + bo);
                #pragma unroll
                for (int mt = 0; mt < 2; mt++) {
                    #pragma unroll
                    for (int j = 0; j < 2; j++)
                        mma_fp16(acc[mt][np * 2 + j], af[mt], bf + 2 * j);
                }
            }
        }
    }

    // Epilogue: fp16 packed-quad stores. Thread owns rows rr0, rr0+8 (mt 0)
    // and rr0+16, rr0+24 (mt 1) — exactly one channel-quad.
    const int rr0  = mBase + warp_m * 32 + (lane >> 2);   // (rr0 & 31) < 8
    const int qidx = ((rr0 >> 5) << 3) | (rr0 & 7);
    __half* qb = g_qh + ((size_t)b * NQ + qidx) * ((size_t)NPIX * 4);
    const int cc0 = nBase + warp_n * 64 + (lane & 3) * 2;
    #pragma unroll
    for (int nt = 0; nt < 8; nt++) {
        const int cc = cc0 + nt * 8;
        __half2 h0 = __float22half2_rn(make_float2(acc[0][nt][0], acc[0][nt][2]));
        __half2 h1 = __float22half2_rn(make_float2(acc[1][nt][0], acc[1][nt][2]));
        __half2 h2 = __float22half2_rn(make_float2(acc[0][nt][1], acc[0][nt][3]));
        __half2 h3 = __float22half2_rn(make_float2(acc[1][nt][1], acc[1][nt][3]));
        uint4 u = make_uint4(h2bits(h0), h2bits(h1), h2bits(h2), h2bits(h3));
        *reinterpret_cast<uint4*>(qb + (size_t)cc * 4) = u;
    }
}

// ---------------------------------------------------------------------------
// Gate: one block per batch
// ---------------------------------------------------------------------------
__global__ __launch_bounds__(256) void gate_kernel(
    const float* __restrict__ w_gate, const float* __restrict__ b_gate)
{
    const int b = blockIdx.x;
    const int tid = threadIdx.x;
    const int lane = tid & 31;
    const int warp = tid >> 5;

    float s[ND] = {0.f, 0.f, 0.f, 0.f};
    for (int c = tid; c < CC; c += 256) {
        float p = g_pooled[b * CC + c] * (1.0f / NPIX);
        #pragma unroll
        for (int i = 0; i < ND; i++) s[i] += p * w_gate[i * CC + c];
    }
    #pragma unroll
    for (int i = 0; i < ND; i++)
        #pragma unroll
        for (int off = 16; off > 0; off >>= 1)
            s[i] += __shfl_xor_sync(0xFFFFFFFFu, s[i], off);

    __shared__ float sred[8][ND];
    if (lane == 0)
        #pragma unroll
        for (int i = 0; i < ND; i++) sred[warp][i] = s[i];
    __syncthreads();
    if (tid == 0) {
        float logits[ND];
        float m = -1e30f;
        #pragma unroll
        for (int i = 0; i < ND; i++) {
            float t = b_gate[i];
            #pragma unroll
            for (int wdx = 0; wdx < 8; wdx++) t += sred[wdx][i];
            logits[i] = t;
            m = fmaxf(m, t);
        }
        float den = 0.f;
        #pragma unroll
        for (int i = 0; i < ND; i++) { logits[i] = __expf(logits[i] - m); den += logits[i]; }
        float inv = 1.f / den;
        #pragma unroll
        for (int i = 0; i < ND; i++) g_gate[b * ND + i] = logits[i] * inv;
    }
}

// ---------------------------------------------------------------------------
// Dilated 3x3 attention + gate, fp16 packed-quad loads (uint2 = 4 channels)
// ---------------------------------------------------------------------------
__global__ __launch_bounds__(128) void attn_kernel(float* __restrict__ out)
{
    const int n  = blockIdx.x * 128 + threadIdx.x;
    const int bh = blockIdx.y;
    const int b  = blockIdx.z;
    const int branch = bh >> 1;
    const int dil    = 1 << branch;
    const int qc     = branch * BD + (bh & 1) * HD;   // multiple of 64

    const int qidx0 = (qc >> 5) << 3;
    const __half* qp = g_qh + ((size_t)b * NQ + qidx0) * ((size_t)NPIX * 4);
    const __half* kp = qp + (size_t)(CC / 4) * NPIX * 4;
    const __half* vp = qp + (size_t)(2 * (CC / 4)) * NPIX * 4;

    const int y  = n >> 6;
    const int xx = n & 63;

    int n2s[9];
    float sc[9];
    #pragma unroll
    for (int p = 0; p < 9; p++) {
        const int y2 = y + (p / 3 - 1) * dil;
        const int x2 = xx + (p % 3 - 1) * dil;
        const bool ok = ((unsigned)y2 < 64u) && ((unsigned)x2 < 64u);
        n2s[p] = ok ? y2 * 64 + x2 : -1;
        sc[p] = 0.f;
    }

    #pragma unroll
    for (int th = 0; th < 2; th++) {
        float qf[32];
        #pragma unroll
        for (int t = 0; t < 8; t++) {
            uint2 u = *reinterpret_cast<const uint2*>(
                qp + ((size_t)(th * 8 + t) * NPIX + n) * 4);
            float2 a = __half22float2(*reinterpret_cast<__half2*>(&u.x));
            float2 c = __half22float2(*reinterpret_cast<__half2*>(&u.y));
            qf[t * 4 + 0] = a.x; qf[t * 4 + 1] = a.y;
            qf[t * 4 + 2] = c.x; qf[t * 4 + 3] = c.y;
        }
        #pragma unroll
        for (int p = 0; p < 9; p++) {
            if (n2s[p] >= 0) {
                float s = 0.f;
                #pragma unroll
                for (int t = 0; t < 8; t++) {
                    uint2 u = *reinterpret_cast<const uint2*>(
                        kp + ((size_t)(th * 8 + t) * NPIX + n2s[p]) * 4);
                    float2 a = __half22float2(*reinterpret_cast<__half2*>(&u.x));
                    float2 c = __half22float2(*reinterpret_cast<__half2*>(&u.y));
                    s = fmaf(qf[t * 4 + 0], a.x, s);
                    s = fmaf(qf[t * 4 + 1], a.y, s);
                    s = fmaf(qf[t * 4 + 2], c.x, s);
                    s = fmaf(qf[t * 4 + 3], c.y, s);
                }
                sc[p] += s;
            }
        }
    }
    #pragma unroll
    for (int p = 0; p < 9; p++) sc[p] *= 0.125f;

    float m = sc[0];
    #pragma unroll
    for (int p = 1; p < 9; p++) m = fmaxf(m, sc[p]);
    float den = 0.f;
    #pragma unroll
    for (int p = 0; p < 9; p++) { sc[p] = __expf(sc[p] - m); den += sc[p]; }
    const float inv = 1.f / den;
    #pragma unroll
    for (int p = 0; p < 9; p++) sc[p] *= inv;

    const float g = g_gate[b * ND + branch];
    float* op = out + ((size_t)b * CC + qc) * NPIX + n;

    #pragma unroll
    for (int th = 0; th < 2; th++) {
        float o[32];
        #pragma unroll
        for (int i = 0; i < 32; i++) o[i] = 0.f;
        #pragma unroll
        for (int p = 0; p < 9; p++) {
            if (n2s[p] >= 0) {
                const float wgt = sc[p];
                #pragma unroll
                for (int t = 0; t < 8; t++) {
                    uint2 u = *reinterpret_cast<const uint2*>(
                        vp + ((size_t)(th * 8 + t) * NPIX + n2s[p]) * 4);
                    float2 a = __half22float2(*reinterpret_cast<__half2*>(&u.x));
                    float2 c = __half22float2(*reinterpret_cast<__half2*>(&u.y));
                    o[t * 4 + 0] = fmaf(wgt, a.x, o[t * 4 + 0]);
                    o[t * 4 + 1] = fmaf(wgt, a.y, o[t * 4 + 1]);
                    o[t * 4 + 2] = fmaf(wgt, c.x, o[t * 4 + 2]);
                    o[t * 4 + 3] = fmaf(wgt, c.y, o[t * 4 + 3]);
                }
            }
        }
        #pragma unroll
        for (int t = 0; t < 8; t++)
            #pragma unroll
            for (int s = 0; s < 4; s++) {
                const int d = th * 32 + t + s * 8;
                op[(size_t)d * NPIX] = o[t * 4 + s] * g;
            }
    }
}

// ---------------------------------------------------------------------------
// Launch
// ---------------------------------------------------------------------------
extern "C" void kernel_launch(void* const* d_in, const int* in_sizes, int n_in,
                              void* d_out, int out_size)
{
    (void)in_sizes; (void)n_in; (void)out_size;
    const float* x      = (const float*)d_in[0];  // (8, 512, 64, 64)
    const float* w_qkv  = (const float*)d_in[1];  // (1536, 512)
    const float* w_gate = (const float*)d_in[2];  // (4, 512)
    const float* b_gate = (const float*)d_in[3];  // (4,)
    float* out = (float*)d_out;                   // (8, 512, 64, 64)

    cudaFuncSetAttribute(gemm_mma_kernel,
                         cudaFuncAttributeMaxDynamicSharedMemorySize, GEMM_SMEM);

    split_w_kernel<<<(OC * CC) / 256, 256>>>(w_qkv);          // + pooled zeroing
    tsx_kernel<<<dim3(NPIX / 32, CC / 32, BB), dim3(32, 8)>>>(x);
    gate_kernel<<<BB, 256>>>(w_gate, b_gate);

    gemm_mma_kernel<<<dim3(OC / 128, NPIX / 128, BB), 256, GEMM_SMEM>>>();

    attn_kernel<<<dim3(NPIX / 128, 2 * ND, BB), 128>>>(out);
}